// round 16
// baseline (speedup 1.0000x reference)
#include <cuda_runtime.h>
#include <cuda_fp16.h>
#include <math.h>
#include <stdint.h>

#define S_LEN 4096
#define B_DIM 32
#define H_DIM 512
#define NROW  (S_LEN * B_DIM)   // 131072

// packing scales: P = 32*Ah + 4096*Al ; Q = 32*Wh + 4096*Wl
// Cpq = 1024*Ah@Wh + 131072*cross + 2^24*lolo
// C   = 0.9921875*C1 + Cpq/131072
#define C1_COEF  0.9921875f
#define CPQ_COEF 7.62939453125e-06f   // 1/131072

// ---------------- device scratch ----------------
// g_Bh[n*512+k] = hi(W[k][n]);  g_Bq = fp16(32*Wh + 4096*(W - Wh))
__device__ __half g_Bh[H_DIM * H_DIM];
__device__ __half g_Bq[H_DIM * H_DIM];
// per-nt partial logits, layout [nt][b*S_LEN + s]
__device__ float g_part[4][NROW];

__device__ __forceinline__ uint32_t smem_u32(const void* p) {
    uint32_t a;
    asm("{ .reg .u64 t; cvta.to.shared.u64 t, %1; cvt.u32.u64 %0, t; }" : "=r"(a) : "l"(p));
    return a;
}

#define LDSM4(r0, r1, r2, r3, addr) \
    asm volatile("ldmatrix.sync.aligned.m8n8.x4.shared.b16 {%0,%1,%2,%3}, [%4];" \
        : "=r"(r0), "=r"(r1), "=r"(r2), "=r"(r3) : "r"(addr))

#define MMA16816(c, a, b0, b1) \
    asm volatile("mma.sync.aligned.m16n8k16.row.col.f32.f16.f16.f32 " \
        "{%0,%1,%2,%3}, {%4,%5,%6,%7}, {%8,%9}, {%0,%1,%2,%3};" \
        : "+f"((c)[0]), "+f"((c)[1]), "+f"((c)[2]), "+f"((c)[3]) \
        : "r"((a)[0]), "r"((a)[1]), "r"((a)[2]), "r"((a)[3]), "r"(b0), "r"(b1))

// ---------------- kernel 0: split W into (hi, packed-q) transposed ----------
__global__ __launch_bounds__(256) void split_w(const float* __restrict__ Wm) {
    int idx = blockIdx.x * 256 + threadIdx.x;   // 0 .. 262143
    int k = idx >> 9, n = idx & 511;
    float v = Wm[idx];
    __half hi = __float2half_rn(v);
    float hif = __half2float(hi);
    g_Bh[n * H_DIM + k] = hi;
    g_Bq[n * H_DIM + k] = __float2half_rn(32.0f * hif + 4096.0f * (v - hif));
}

// produce (hi, packed-q) fp16x2 pairs from a float4
__device__ __forceinline__ void split4q(float4 v, uint2& hi, uint2& qq) {
    __half2 h01 = __floats2half2_rn(v.x, v.y);
    __half2 h23 = __floats2half2_rn(v.z, v.w);
    float2 f01 = __half22float2(h01);
    float2 f23 = __half22float2(h23);
    __half2 q01 = __floats2half2_rn(32.0f * f01.x + 4096.0f * (v.x - f01.x),
                                    32.0f * f01.y + 4096.0f * (v.y - f01.y));
    __half2 q23 = __floats2half2_rn(32.0f * f23.x + 4096.0f * (v.z - f23.x),
                                    32.0f * f23.y + 4096.0f * (v.w - f23.y));
    hi.x = *(uint32_t*)&h01; hi.y = *(uint32_t*)&h23;
    qq.x = *(uint32_t*)&q01; qq.y = *(uint32_t*)&q23;
}

// ---------------- kernel 1: 2-GEMM packed-split bilinear -> partial logits ---
// grid 4096: bid>>2 = row-block (128 rows), bid&3 = nt (128-col chunk of N)
// rows r = s*32+b; A[m] = Enc[r-32] (rows r<32 garbage, fixed by kernel 2)
// g_part[nt][b*S+s] = sum_{n in chunk} C[r,n] * Enc[r,n] * hid[b,n]
//
// SMEM per buffer: 4 tiles (A_hi, A_q, B_hi, B_q), 128 rows x 40 halfs (80B)
#define TSTRIDE_B 80
#define TILE_B    (128 * TSTRIDE_B)   // 10240
#define BUF_B     (4 * TILE_B)        // 40960
#define SMEM_TOTAL (2 * BUF_B)        // 81920

__global__ __launch_bounds__(256, 1) void bilinear_hmma(
    const float* __restrict__ enc, const float* __restrict__ hid)
{
    extern __shared__ char smem[];
    const uint32_t sb = smem_u32(smem);
    const int tid = threadIdx.x;
    const int lane = tid & 31, wid = tid >> 5;
    const int warp_m = wid >> 2;     // 0..1 : m offset 64*warp_m
    const int warp_n = wid & 3;      // 0..3 : n offset 32*warp_n
    const int m0 = (blockIdx.x >> 2) * 128;
    const int nt = blockIdx.x & 3;
    const int nbase = nt * 128;

    // ---- fill mapping: slot = tid + i*256; row = slot>>3; c4 = (slot&7)*4 ----
    const int rrow = tid >> 3;           // 0..31
    const int c4   = (tid & 7) * 4;      // 0,4,..,28
    const float* aptr[4];
    uint32_t asts[4];
#pragma unroll
    for (int i = 0; i < 4; ++i) {
        const int row = rrow + i * 32;
        long gr = (long)m0 + row - B_DIM; if (gr < 0) gr = 0;
        aptr[i] = enc + (size_t)gr * H_DIM + c4;
        asts[i] = (uint32_t)(row * TSTRIDE_B + c4 * 2);
    }

    // ---- ldmatrix addresses ----
    uint32_t a_addr[4];
#pragma unroll
    for (int mt = 0; mt < 4; ++mt)
        a_addr[mt] = sb + (uint32_t)((warp_m * 64 + mt * 16 + (lane & 15)) * TSTRIDE_B
                                     + ((lane >> 4) & 1) * 16);
    uint32_t b_addr[2];
#pragma unroll
    for (int p = 0; p < 2; ++p)
        b_addr[p] = sb + 2 * TILE_B + (uint32_t)((warp_n * 32 + p * 16 + (lane & 15)) * TSTRIDE_B
                                                 + ((lane >> 4) & 1) * 16);

    float chh[4][4][4];   // Ah@Wh
    float cpq[4][4][4];   // P@Q
#pragma unroll
    for (int mt = 0; mt < 4; ++mt)
#pragma unroll
        for (int ntl = 0; ntl < 4; ++ntl)
#pragma unroll
            for (int q = 0; q < 4; ++q) { chh[mt][ntl][q] = 0.f; cpq[mt][ntl][q] = 0.f; }

    float4 av[4];
    uint2 bh[4], bq[4];

    // ---- prologue: LDG + STS stage 0 -> buf 0 ----
#pragma unroll
    for (int i = 0; i < 4; ++i) av[i] = *(const float4*)(aptr[i]);
#pragma unroll
    for (int i = 0; i < 4; ++i) {
        const size_t o = (size_t)(nbase + rrow + i * 32) * H_DIM + c4;
        bh[i] = *(const uint2*)(g_Bh + o);
        bq[i] = *(const uint2*)(g_Bq + o);
    }
    {
        char* base = smem;
#pragma unroll
        for (int i = 0; i < 4; ++i) {
            uint2 hi, qq; split4q(av[i], hi, qq);
            *(uint2*)(base + asts[i])              = hi;
            *(uint2*)(base + TILE_B + asts[i])     = qq;
            *(uint2*)(base + 2 * TILE_B + asts[i]) = bh[i];
            *(uint2*)(base + 3 * TILE_B + asts[i]) = bq[i];
        }
    }
    __syncthreads();

#pragma unroll 1
    for (int st = 0; st < 16; ++st) {
        const int buf = st & 1;
        if (st < 15) {
            const int kb = (st + 1) * 32;
#pragma unroll
            for (int i = 0; i < 4; ++i) av[i] = *(const float4*)(aptr[i] + kb);
#pragma unroll
            for (int i = 0; i < 4; ++i) {
                const size_t o = (size_t)(nbase + rrow + i * 32) * H_DIM + kb + c4;
                bh[i] = *(const uint2*)(g_Bh + o);
                bq[i] = *(const uint2*)(g_Bq + o);
            }
        }

        const uint32_t boff = buf ? (uint32_t)BUF_B : 0u;
#pragma unroll
        for (int kk = 0; kk < 2; ++kk) {
            const uint32_t koff = boff + kk * 32;   // 16 halfs = 32B per k16
            uint32_t af[4][4];
            uint32_t bf[4][2];
            // ---- GEMM 1: Ah @ Wh ----
#pragma unroll
            for (int mt = 0; mt < 4; ++mt)
                LDSM4(af[mt][0], af[mt][1], af[mt][2], af[mt][3], a_addr[mt] + koff);
#pragma unroll
            for (int p = 0; p < 2; ++p) {
                uint32_t r0, r1, r2, r3;
                LDSM4(r0, r1, r2, r3, b_addr[p] + koff);
                bf[2 * p][0] = r0;     bf[2 * p][1] = r2;
                bf[2 * p + 1][0] = r1; bf[2 * p + 1][1] = r3;
            }
#pragma unroll
            for (int mt = 0; mt < 4; ++mt)
#pragma unroll
                for (int ntl = 0; ntl < 4; ++ntl)
                    MMA16816(chh[mt][ntl], af[mt], bf[ntl][0], bf[ntl][1]);
            // ---- GEMM 2: P @ Q (packed tiles at +TILE_B) ----
#pragma unroll
            for (int mt = 0; mt < 4; ++mt)
                LDSM4(af[mt][0], af[mt][1], af[mt][2], af[mt][3],
                      a_addr[mt] + koff + TILE_B);
#pragma unroll
            for (int p = 0; p < 2; ++p) {
                uint32_t r0, r1, r2, r3;
                LDSM4(r0, r1, r2, r3, b_addr[p] + koff + TILE_B);
                bf[2 * p][0] = r0;     bf[2 * p][1] = r2;
                bf[2 * p + 1][0] = r1; bf[2 * p + 1][1] = r3;
            }
#pragma unroll
            for (int mt = 0; mt < 4; ++mt)
#pragma unroll
                for (int ntl = 0; ntl < 4; ++ntl)
                    MMA16816(cpq[mt][ntl], af[mt], bf[ntl][0], bf[ntl][1]);
        }

        if (st < 15) {
            char* base = smem + (buf ^ 1) * BUF_B;
#pragma unroll
            for (int i = 0; i < 4; ++i) {
                uint2 hi, qq; split4q(av[i], hi, qq);
                *(uint2*)(base + asts[i])              = hi;
                *(uint2*)(base + TILE_B + asts[i])     = qq;
                *(uint2*)(base + 2 * TILE_B + asts[i]) = bh[i];
                *(uint2*)(base + 3 * TILE_B + asts[i]) = bq[i];
            }
        }
        __syncthreads();
    }

    // ---- fused epilogue: rowacc = (C1_COEF*chh + CPQ_COEF*cpq) .* (Enc.*hid) ----
    float rowacc[4][2];
#pragma unroll
    for (int mt = 0; mt < 4; ++mt) {
#pragma unroll
        for (int j = 0; j < 2; ++j) {
            const int r = m0 + warp_m * 64 + mt * 16 + (lane >> 2) + j * 8;
            const float* er = enc + (size_t)r * H_DIM;
            const float* hr = hid + (size_t)(r & 31) * H_DIM;
            float acc = 0.f;
#pragma unroll
            for (int ntl = 0; ntl < 4; ++ntl) {
                const int col = nbase + warp_n * 32 + ntl * 8 + (lane & 3) * 2;
                const float2 e = *(const float2*)(er + col);
                const float2 h = *(const float2*)(hr + col);
                const float c0 = fmaf(cpq[mt][ntl][j * 2 + 0], CPQ_COEF,
                                      C1_COEF * chh[mt][ntl][j * 2 + 0]);
                const float c1 = fmaf(cpq[mt][ntl][j * 2 + 1], CPQ_COEF,
                                      C1_COEF * chh[mt][ntl][j * 2 + 1]);
                acc = fmaf(c0, e.x * h.x, acc);
                acc = fmaf(c1, e.y * h.y, acc);
            }
            rowacc[mt][j] = acc;
        }
    }

    // ---- reduce: quad lanes (cols) -> shared rows -> partial store ----
    __syncthreads();
    float* srow = (float*)smem;
    if (tid < 128) srow[tid] = 0.f;
    __syncthreads();
#pragma unroll
    for (int mt = 0; mt < 4; ++mt)
#pragma unroll
        for (int j = 0; j < 2; ++j) {
            float v = rowacc[mt][j];
            v += __shfl_xor_sync(0xffffffffu, v, 1);
            v += __shfl_xor_sync(0xffffffffu, v, 2);
            if ((lane & 3) == 0)
                atomicAdd(&srow[warp_m * 64 + mt * 16 + (lane >> 2) + j * 8], v);
        }
    __syncthreads();
    if (tid < 128) {
        const int r = m0 + tid;
        g_part[nt][(r & 31) * S_LEN + (r >> 5)] = srow[tid];   // [b*4096 + s]
    }
}

// ---------------- kernel 2: sum partials + affect + s==0 fixup + softmax -----
__global__ __launch_bounds__(256) void softmax_finalize(
    const float* __restrict__ enc, const float* __restrict__ hid,
    const float* __restrict__ emb, const float* __restrict__ aff,
    float* __restrict__ out)
{
    const int b = blockIdx.x;
    const int tid = threadIdx.x;
    const int lane = tid & 31, wid = tid >> 5;
    __shared__ float red[8][4];
    __shared__ float fin[4];
    __shared__ float rmax[8];
    __shared__ float rsum[8];

    float a0 = 0.f, a1 = 0.f, a2 = 0.f, e0 = 0.f;
    for (int h = tid; h < H_DIM; h += 256) {
        const float hv = hid[b * H_DIM + h];
        a0 += hv * aff[h * 3 + 0];
        a1 += hv * aff[h * 3 + 1];
        a2 += hv * aff[h * 3 + 2];
        e0 += hv * enc[b * H_DIM + h];
    }
#pragma unroll
    for (int m = 16; m; m >>= 1) {
        a0 += __shfl_xor_sync(~0u, a0, m);
        a1 += __shfl_xor_sync(~0u, a1, m);
        a2 += __shfl_xor_sync(~0u, a2, m);
        e0 += __shfl_xor_sync(~0u, e0, m);
    }
    if (lane == 0) { red[wid][0] = a0; red[wid][1] = a1; red[wid][2] = a2; red[wid][3] = e0; }
    __syncthreads();
    if (tid < 4) {
        float s = 0.f;
        for (int w = 0; w < 8; ++w) s += red[w][tid];
        fin[tid] = s;
    }
    __syncthreads();
    const float A0 = fin[0], A1 = fin[1], A2 = fin[2], E0 = fin[3];

    float l[16];
    float mx = -INFINITY;
#pragma unroll
    for (int it = 0; it < 16; ++it) {
        const int s = tid + it * 256;
        const int idx = b * S_LEN + s;
        float v;
        if (s == 0) v = E0;
        else v = (g_part[0][idx] + g_part[1][idx]) + (g_part[2][idx] + g_part[3][idx]);
        const float* ep = emb + ((size_t)s * B_DIM + b) * 3;
        v += A0 * ep[0] + A1 * ep[1] + A2 * ep[2];
        l[it] = v;
        mx = fmaxf(mx, v);
    }
#pragma unroll
    for (int m = 16; m; m >>= 1) mx = fmaxf(mx, __shfl_xor_sync(~0u, mx, m));
    if (lane == 0) rmax[wid] = mx;
    __syncthreads();
    if (tid == 0) {
        float m2 = rmax[0];
        for (int w = 1; w < 8; ++w) m2 = fmaxf(m2, rmax[w]);
        rmax[0] = m2;
    }
    __syncthreads();
    const float MX = rmax[0];

    float sum = 0.f;
#pragma unroll
    for (int it = 0; it < 16; ++it) { l[it] = expf(l[it] - MX); sum += l[it]; }
#pragma unroll
    for (int m = 16; m; m >>= 1) sum += __shfl_xor_sync(~0u, sum, m);
    if (lane == 0) rsum[wid] = sum;
    __syncthreads();
    if (tid == 0) {
        float s2 = 0.f;
        for (int w = 0; w < 8; ++w) s2 += rsum[w];
        rsum[0] = s2;
    }
    __syncthreads();
    const float inv = 1.0f / rsum[0];
#pragma unroll
    for (int it = 0; it < 16; ++it)
        out[b * S_LEN + tid + it * 256] = l[it] * inv;
}

// ---------------- launch ----------------
extern "C" void kernel_launch(void* const* d_in, const int* in_sizes, int n_in,
                              void* d_out, int out_size) {
    const float *hid = nullptr, *enc = nullptr, *emb = nullptr, *Wm = nullptr, *aff = nullptr;
    for (int i = 0; i < n_in; ++i) {
        switch (in_sizes[i]) {
            case 16384:    hid = (const float*)d_in[i]; break;  // hidden [1,32,512]
            case 67108864: enc = (const float*)d_in[i]; break;  // encoder_outputs [4096,32,512]
            case 393216:   emb = (const float*)d_in[i]; break;  // embedding [4096,32,3]
            case 262144:   Wm  = (const float*)d_in[i]; break;  // bigram_matrix [512,512]
            case 1536:     aff = (const float*)d_in[i]; break;  // affect_matrix [512,3]
        }
    }
    float* out = (float*)d_out;  // [32,1,4096] fp32

    cudaFuncSetAttribute(bilinear_hmma,
                         cudaFuncAttributeMaxDynamicSharedMemorySize, SMEM_TOTAL);

    split_w<<<(H_DIM * H_DIM) / 256, 256>>>(Wm);
    bilinear_hmma<<<4096, 256, SMEM_TOTAL>>>(enc, hid);
    softmax_finalize<<<B_DIM, 256>>>(enc, hid, emb, aff, out);
}

// round 17
// speedup vs baseline: 1.2442x; 1.2442x over previous
#include <cuda_runtime.h>
#include <cuda_fp16.h>
#include <math.h>
#include <stdint.h>

#define S_LEN 4096
#define B_DIM 32
#define H_DIM 512
#define NROW  (S_LEN * B_DIM)   // 131072

// packing scales: P = 32*Ah + 4096*Al ; Q = 32*Wh + 4096*Wl
// Cpq = 1024*Ah@Wh + 131072*cross + 2^24*lolo
// C   = 0.9921875*C1 + Cpq/131072
#define C1_COEF  0.9921875f
#define CPQ_COEF 7.62939453125e-06f   // 1/131072

// ---------------- device scratch: transposed fp16 planes of W ----------------
__device__ __half g_Bh[H_DIM * H_DIM];   // hi(W[k][n]) at [n][k]
__device__ __half g_Bq[H_DIM * H_DIM];   // fp16(32*Wh + 4096*(W-Wh))

__device__ __forceinline__ uint32_t smem_u32(const void* p) {
    uint32_t a;
    asm("{ .reg .u64 t; cvta.to.shared.u64 t, %1; cvt.u32.u64 %0, t; }" : "=r"(a) : "l"(p));
    return a;
}

#define LDSM4(r0, r1, r2, r3, addr) \
    asm volatile("ldmatrix.sync.aligned.m8n8.x4.shared.b16 {%0,%1,%2,%3}, [%4];" \
        : "=r"(r0), "=r"(r1), "=r"(r2), "=r"(r3) : "r"(addr))

#define MMA16816(c, a, b0, b1) \
    asm volatile("mma.sync.aligned.m16n8k16.row.col.f32.f16.f16.f32 " \
        "{%0,%1,%2,%3}, {%4,%5,%6,%7}, {%8,%9}, {%0,%1,%2,%3};" \
        : "+f"((c)[0]), "+f"((c)[1]), "+f"((c)[2]), "+f"((c)[3]) \
        : "r"((a)[0]), "r"((a)[1]), "r"((a)[2]), "r"((a)[3]), "r"(b0), "r"(b1))

#define CP8(dst, src) \
    asm volatile("cp.async.ca.shared.global [%0], [%1], 8;" :: "r"(dst), "l"(src))
#define CP_COMMIT() asm volatile("cp.async.commit_group;" ::: "memory")
#define CP_WAIT0()  asm volatile("cp.async.wait_group 0;" ::: "memory")

// ---------------- kernel 0: split W into (hi, packed-q) transposed ----------
__global__ __launch_bounds__(256) void split_w(const float* __restrict__ Wm) {
    int idx = blockIdx.x * 256 + threadIdx.x;   // 0 .. 262143
    int k = idx >> 9, n = idx & 511;
    float v = Wm[idx];
    __half hi = __float2half_rn(v);
    float hif = __half2float(hi);
    g_Bh[n * H_DIM + k] = hi;
    g_Bq[n * H_DIM + k] = __float2half_rn(32.0f * hif + 4096.0f * (v - hif));
}

// produce (hi, packed-q) fp16x2 pairs from a float4
__device__ __forceinline__ void split4q(float4 v, uint2& hi, uint2& qq) {
    __half2 h01 = __floats2half2_rn(v.x, v.y);
    __half2 h23 = __floats2half2_rn(v.z, v.w);
    float2 f01 = __half22float2(h01);
    float2 f23 = __half22float2(h23);
    __half2 q01 = __floats2half2_rn(32.0f * f01.x + 4096.0f * (v.x - f01.x),
                                    32.0f * f01.y + 4096.0f * (v.y - f01.y));
    __half2 q23 = __floats2half2_rn(32.0f * f23.x + 4096.0f * (v.z - f23.x),
                                    32.0f * f23.y + 4096.0f * (v.w - f23.y));
    hi.x = *(uint32_t*)&h01; hi.y = *(uint32_t*)&h23;
    qq.x = *(uint32_t*)&q01; qq.y = *(uint32_t*)&q23;
}

// ---------------- kernel 1: 2-GEMM packed-split bilinear -> logits -----------
// rows r = s*32+b; A[m] = Enc[r-32] (rows r<32 garbage, fixed by kernel 2)
// C1 = Ah@Wh ; Cpq = P@Q ; C = C1_COEF*C1 + CPQ_COEF*Cpq
// logit[r] = sum_n C[r,n] * Enc[r,n] * hid[b,n]
//
// BK=64. SMEM per buffer: 4 tiles (A_hi, A_q, B_hi, B_q), 128 rows x 72 halfs
#define TSTRIDE_B 144
#define TILE_B    (128 * TSTRIDE_B)   // 18432
#define BUF_B     (4 * TILE_B)        // 73728
#define SMEM_TOTAL (2 * BUF_B)        // 147456

__global__ __launch_bounds__(256, 1) void bilinear_hmma(
    const float* __restrict__ enc, const float* __restrict__ hid,
    float* __restrict__ logits)
{
    extern __shared__ char smem[];
    const uint32_t sb = smem_u32(smem);
    const int tid = threadIdx.x;
    const int lane = tid & 31, wid = tid >> 5;
    const int warp_m = wid >> 2;     // 0..1 : m offset 64*warp_m
    const int warp_n = wid & 3;      // 0..3 : n offset 32*warp_n
    const int m0 = blockIdx.x * 128;

    // ---- fill mapping: slot = tid + i*256 (i<8); row = slot>>4; c = slot&15
    const int rrow = tid >> 4;           // 0..15
    const int cc   = tid & 15;           // chunk: 4 floats / 4 halfs (8B)
    const float* aptr[8];
    uint32_t asts[8];
    uint32_t brow_off[8];                // (row)*H_DIM + cc*4  (add nbase, kb)
#pragma unroll
    for (int i = 0; i < 8; ++i) {
        const int row = rrow + i * 16;
        long gr = (long)m0 + row - B_DIM; if (gr < 0) gr = 0;
        aptr[i]     = enc + (size_t)gr * H_DIM + cc * 4;
        asts[i]     = (uint32_t)(row * TSTRIDE_B + cc * 8);
        brow_off[i] = (uint32_t)(row * H_DIM + cc * 4);
    }

    // ---- ldmatrix addresses ----
    uint32_t a_addr[4];
#pragma unroll
    for (int mt = 0; mt < 4; ++mt)
        a_addr[mt] = sb + (uint32_t)((warp_m * 64 + mt * 16 + (lane & 15)) * TSTRIDE_B
                                     + ((lane >> 4) & 1) * 16);
    uint32_t b_addr[2];
#pragma unroll
    for (int p = 0; p < 2; ++p)
        b_addr[p] = sb + 2 * TILE_B + (uint32_t)((warp_n * 32 + p * 16 + (lane & 15)) * TSTRIDE_B
                                                 + ((lane >> 4) & 1) * 16);

    float rowacc[4][2];
#pragma unroll
    for (int mt = 0; mt < 4; ++mt) { rowacc[mt][0] = 0.f; rowacc[mt][1] = 0.f; }

#pragma unroll 1
    for (int nt = 0; nt < 4; ++nt) {
        const int nbase = nt * 128;
        const uint32_t bgoff = (uint32_t)nbase * H_DIM;

        float chh[4][4][4];   // Ah@Wh
        float cpq[4][4][4];   // P@Q
#pragma unroll
        for (int mt = 0; mt < 4; ++mt)
#pragma unroll
            for (int ntl = 0; ntl < 4; ++ntl)
#pragma unroll
                for (int q = 0; q < 4; ++q) { chh[mt][ntl][q] = 0.f; cpq[mt][ntl][q] = 0.f; }

        float4 av[8];

        // issue B cp.async for stage `stg` into buffer `buf`
        auto cpB = [&](int stg, int buf) {
            const uint32_t kb = stg * 64;
            const uint32_t bb = sb + buf * (uint32_t)BUF_B;
#pragma unroll
            for (int i = 0; i < 8; ++i) {
                const uint32_t so = bgoff + brow_off[i] + kb;
                CP8(bb + 2 * TILE_B + asts[i], g_Bh + so);
                CP8(bb + 3 * TILE_B + asts[i], g_Bq + so);
            }
            CP_COMMIT();
        };
        auto ldA = [&](int stg) {
            const int kb = stg * 64;
#pragma unroll
            for (int i = 0; i < 8; ++i) av[i] = *(const float4*)(aptr[i] + kb);
        };
        auto stA = [&](int buf) {
            char* base = smem + buf * BUF_B;
#pragma unroll
            for (int i = 0; i < 8; ++i) {
                uint2 hi, qq; split4q(av[i], hi, qq);
                *(uint2*)(base + asts[i])          = hi;
                *(uint2*)(base + TILE_B + asts[i]) = qq;
            }
        };

        // ---- prologue: stage 0 -> buf 0 ----
        cpB(0, 0);
        ldA(0);
        stA(0);
        CP_WAIT0();
        __syncthreads();

#pragma unroll 1
        for (int st = 0; st < 8; ++st) {
            const int buf = st & 1;
            if (st < 7) { cpB(st + 1, buf ^ 1); ldA(st + 1); }

            const uint32_t boff = buf ? (uint32_t)BUF_B : 0u;
#pragma unroll
            for (int kk = 0; kk < 4; ++kk) {
                const uint32_t koff = boff + kk * 32;   // 16 halfs = 32B per k16
                uint32_t af[4][4];
                uint32_t bf[4][2];
                // ---- GEMM 1: Ah @ Wh ----
#pragma unroll
                for (int mt = 0; mt < 4; ++mt)
                    LDSM4(af[mt][0], af[mt][1], af[mt][2], af[mt][3], a_addr[mt] + koff);
#pragma unroll
                for (int p = 0; p < 2; ++p) {
                    uint32_t r0, r1, r2, r3;
                    LDSM4(r0, r1, r2, r3, b_addr[p] + koff);
                    bf[2 * p][0] = r0;     bf[2 * p][1] = r2;
                    bf[2 * p + 1][0] = r1; bf[2 * p + 1][1] = r3;
                }
#pragma unroll
                for (int mt = 0; mt < 4; ++mt)
#pragma unroll
                    for (int ntl = 0; ntl < 4; ++ntl)
                        MMA16816(chh[mt][ntl], af[mt], bf[ntl][0], bf[ntl][1]);
                // ---- GEMM 2: P @ Q (packed tiles at +TILE_B) ----
#pragma unroll
                for (int mt = 0; mt < 4; ++mt)
                    LDSM4(af[mt][0], af[mt][1], af[mt][2], af[mt][3],
                          a_addr[mt] + koff + TILE_B);
#pragma unroll
                for (int p = 0; p < 2; ++p) {
                    uint32_t r0, r1, r2, r3;
                    LDSM4(r0, r1, r2, r3, b_addr[p] + koff + TILE_B);
                    bf[2 * p][0] = r0;     bf[2 * p][1] = r2;
                    bf[2 * p + 1][0] = r1; bf[2 * p + 1][1] = r3;
                }
#pragma unroll
                for (int mt = 0; mt < 4; ++mt)
#pragma unroll
                    for (int ntl = 0; ntl < 4; ++ntl)
                        MMA16816(cpq[mt][ntl], af[mt], bf[ntl][0], bf[ntl][1]);
            }

            if (st < 7) stA(buf ^ 1);
            CP_WAIT0();
            __syncthreads();
        }

        // ---- fused epilogue: rowacc += (C1_COEF*chh + CPQ_COEF*cpq) .* (Enc.*hid) ----
#pragma unroll
        for (int mt = 0; mt < 4; ++mt) {
#pragma unroll
            for (int j = 0; j < 2; ++j) {
                const int r = m0 + warp_m * 64 + mt * 16 + (lane >> 2) + j * 8;
                const float* er = enc + (size_t)r * H_DIM;
                const float* hr = hid + (size_t)(r & 31) * H_DIM;
                float acc = 0.f;
#pragma unroll
                for (int ntl = 0; ntl < 4; ++ntl) {
                    const int col = nbase + warp_n * 32 + ntl * 8 + (lane & 3) * 2;
                    const float2 e = *(const float2*)(er + col);
                    const float2 h = *(const float2*)(hr + col);
                    const float c0 = fmaf(cpq[mt][ntl][j * 2 + 0], CPQ_COEF,
                                          C1_COEF * chh[mt][ntl][j * 2 + 0]);
                    const float c1 = fmaf(cpq[mt][ntl][j * 2 + 1], CPQ_COEF,
                                          C1_COEF * chh[mt][ntl][j * 2 + 1]);
                    acc = fmaf(c0, e.x * h.x, acc);
                    acc = fmaf(c1, e.y * h.y, acc);
                }
                rowacc[mt][j] += acc;
            }
        }
        __syncthreads();   // buffers dead before next nt prologue
    }

    // ---- reduce: quad lanes (cols) -> shared rows -> global ----
    float* srow = (float*)smem;
    if (tid < 128) srow[tid] = 0.f;
    __syncthreads();
#pragma unroll
    for (int mt = 0; mt < 4; ++mt)
#pragma unroll
        for (int j = 0; j < 2; ++j) {
            float v = rowacc[mt][j];
            v += __shfl_xor_sync(0xffffffffu, v, 1);
            v += __shfl_xor_sync(0xffffffffu, v, 2);
            if ((lane & 3) == 0)
                atomicAdd(&srow[warp_m * 64 + mt * 16 + (lane >> 2) + j * 8], v);
        }
    __syncthreads();
    if (tid < 128) {
        const int r = m0 + tid;
        logits[(r & 31) * S_LEN + (r >> 5)] = srow[tid];   // out[b*4096 + s]
    }
}

// ---------------- kernel 2: affect term + s==0 fixup + softmax ----------------
__global__ __launch_bounds__(256) void softmax_finalize(
    const float* __restrict__ enc, const float* __restrict__ hid,
    const float* __restrict__ emb, const float* __restrict__ aff,
    float* __restrict__ out)
{
    const int b = blockIdx.x;
    const int tid = threadIdx.x;
    const int lane = tid & 31, wid = tid >> 5;
    __shared__ float red[8][4];
    __shared__ float fin[4];
    __shared__ float rmax[8];
    __shared__ float rsum[8];

    float a0 = 0.f, a1 = 0.f, a2 = 0.f, e0 = 0.f;
    for (int h = tid; h < H_DIM; h += 256) {
        const float hv = hid[b * H_DIM + h];
        a0 += hv * aff[h * 3 + 0];
        a1 += hv * aff[h * 3 + 1];
        a2 += hv * aff[h * 3 + 2];
        e0 += hv * enc[b * H_DIM + h];
    }
#pragma unroll
    for (int m = 16; m; m >>= 1) {
        a0 += __shfl_xor_sync(~0u, a0, m);
        a1 += __shfl_xor_sync(~0u, a1, m);
        a2 += __shfl_xor_sync(~0u, a2, m);
        e0 += __shfl_xor_sync(~0u, e0, m);
    }
    if (lane == 0) { red[wid][0] = a0; red[wid][1] = a1; red[wid][2] = a2; red[wid][3] = e0; }
    __syncthreads();
    if (tid < 4) {
        float s = 0.f;
        for (int w = 0; w < 8; ++w) s += red[w][tid];
        fin[tid] = s;
    }
    __syncthreads();
    const float A0 = fin[0], A1 = fin[1], A2 = fin[2], E0 = fin[3];

    float l[16];
    float mx = -INFINITY;
#pragma unroll
    for (int it = 0; it < 16; ++it) {
        const int s = tid + it * 256;
        float v = (s == 0) ? E0 : out[b * S_LEN + s];
        const float* ep = emb + ((size_t)s * B_DIM + b) * 3;
        v += A0 * ep[0] + A1 * ep[1] + A2 * ep[2];
        l[it] = v;
        mx = fmaxf(mx, v);
    }
#pragma unroll
    for (int m = 16; m; m >>= 1) mx = fmaxf(mx, __shfl_xor_sync(~0u, mx, m));
    if (lane == 0) rmax[wid] = mx;
    __syncthreads();
    if (tid == 0) {
        float m2 = rmax[0];
        for (int w = 1; w < 8; ++w) m2 = fmaxf(m2, rmax[w]);
        rmax[0] = m2;
    }
    __syncthreads();
    const float MX = rmax[0];

    float sum = 0.f;
#pragma unroll
    for (int it = 0; it < 16; ++it) { l[it] = expf(l[it] - MX); sum += l[it]; }
#pragma unroll
    for (int m = 16; m; m >>= 1) sum += __shfl_xor_sync(~0u, sum, m);
    if (lane == 0) rsum[wid] = sum;
    __syncthreads();
    if (tid == 0) {
        float s2 = 0.f;
        for (int w = 0; w < 8; ++w) s2 += rsum[w];
        rsum[0] = s2;
    }
    __syncthreads();
    const float inv = 1.0f / rsum[0];
#pragma unroll
    for (int it = 0; it < 16; ++it)
        out[b * S_LEN + tid + it * 256] = l[it] * inv;
}

// ---------------- launch ----------------
extern "C" void kernel_launch(void* const* d_in, const int* in_sizes, int n_in,
                              void* d_out, int out_size) {
    const float *hid = nullptr, *enc = nullptr, *emb = nullptr, *Wm = nullptr, *aff = nullptr;
    for (int i = 0; i < n_in; ++i) {
        switch (in_sizes[i]) {
            case 16384:    hid = (const float*)d_in[i]; break;  // hidden [1,32,512]
            case 67108864: enc = (const float*)d_in[i]; break;  // encoder_outputs [4096,32,512]
            case 393216:   emb = (const float*)d_in[i]; break;  // embedding [4096,32,3]
            case 262144:   Wm  = (const float*)d_in[i]; break;  // bigram_matrix [512,512]
            case 1536:     aff = (const float*)d_in[i]; break;  // affect_matrix [512,3]
        }
    }
    float* out = (float*)d_out;  // [32,1,4096] fp32; logits scratch then softmax

    cudaFuncSetAttribute(bilinear_hmma,
                         cudaFuncAttributeMaxDynamicSharedMemorySize, SMEM_TOTAL);

    split_w<<<(H_DIM * H_DIM) / 256, 256>>>(Wm);
    bilinear_hmma<<<(S_LEN * B_DIM) / 128, 256, SMEM_TOTAL>>>(enc, hid, out);
    softmax_finalize<<<B_DIM, 256>>>(enc, hid, emb, aff, out);
}